// round 11
// baseline (speedup 1.0000x reference)
#include <cuda_runtime.h>
#include <cstdint>

#define NSEQ 512
#define DMODEL 512
#define DH 64
#define NH 8
#define KTOP 51
#define SCALE 2.8284271247461903f   // dh^0.25

// scratch (allocation-free rule: __device__ globals)
__device__ float g_Q[NSEQ * DMODEL];
__device__ float g_K[NSEQ * DMODEL];
__device__ float g_V[NSEQ * DMODEL];
__device__ float g_ctx[NSEQ * DMODEL];
__device__ float g_qkvp[12 * NSEQ * DMODEL];  // qkv split-K partials
__device__ float g_outp[8 * NSEQ * DMODEL];   // out split-K partials

// ---------------------------------------------------------------------------
// cp.async + f32x2 helpers
// ---------------------------------------------------------------------------
__device__ __forceinline__ void cp16(uint32_t dst, const void* src) {
    asm volatile("cp.async.cg.shared.global [%0], [%1], 16;" :: "r"(dst), "l"(src));
}
__device__ __forceinline__ void cp_commit() { asm volatile("cp.async.commit_group;"); }
__device__ __forceinline__ void cp_wait0()  { asm volatile("cp.async.wait_group 0;"); }

__device__ __forceinline__ unsigned long long dup2(float x) {
    unsigned long long r;
    asm("mov.b64 %0, {%1, %1};" : "=l"(r) : "r"(__float_as_uint(x)));
    return r;
}
__device__ __forceinline__ void fma2(unsigned long long& d,
                                     unsigned long long a, unsigned long long b) {
    asm("fma.rn.f32x2 %0, %1, %2, %0;" : "+l"(d) : "l"(a), "l"(b));
}

// ---------------------------------------------------------------------------
// fp32 GEMM partial with packed f32x2 (bit-identical to scalar FFMA):
// Cp(128x64) = A * B^T over one K slice. 128 threads, micro 8 rows x 4 col-pairs.
// ---------------------------------------------------------------------------
#define A_F4   1032                      // 8*129 per buf
#define B_F    (32 * 66)                 // per buf
#define GEMM_SMEM_BYTES (2 * A_F4 * 16 + 2 * B_F * 4)

__device__ __forceinline__ void gemm128x64(const float* __restrict__ A,
                                           const float* __restrict__ B,
                                           float* __restrict__ Cp,
                                           int kbase, int kiters)
{
    extern __shared__ float4 gsm4[];
    float4* As4 = gsm4;                         // 2 * A_F4
    float*  BPf = (float*)(gsm4 + 2 * A_F4);    // 2 * B_F
    const int t  = threadIdx.x;
    const int mr = t & 15;              // rows mr + 16*i
    const int ng = t >> 4;              // col-pairs 2*(ng+8p)
    const int m0 = blockIdx.y * 128;
    const int n0 = blockIdx.x * 64;

    const uint32_t sA = (uint32_t)__cvta_generic_to_shared(As4);

    float4 pb[4];

    auto issueA = [&](int kit, int buf) {
        const int k0 = kbase + (kit << 5);
#pragma unroll
        for (int i = 0; i < 8; i++) {
            const int f = t + (i << 7);
            const int m = f >> 3, kq = f & 7;
            cp16(sA + (uint32_t)((buf * A_F4 + kq * 129 + m) << 4),
                 &A[(m0 + m) * 512 + k0 + (kq << 2)]);
        }
        cp_commit();
    };
    auto ldgB = [&](int kit) {
        const int k0 = kbase + (kit << 5);
#pragma unroll
        for (int i = 0; i < 4; i++) {
            const int f = t + (i << 7);
            pb[i] = *(const float4*)&B[(n0 + (f >> 3)) * 512 + k0 + ((f & 7) << 2)];
        }
    };
    auto stsB = [&](int buf) {
        float* Bb = BPf + buf * B_F;
#pragma unroll
        for (int i = 0; i < 4; i++) {
            const int f = t + (i << 7);
            const int n = f >> 3, kq = f & 7;
            Bb[(4 * kq + 0) * 66 + n] = pb[i].x;
            Bb[(4 * kq + 1) * 66 + n] = pb[i].y;
            Bb[(4 * kq + 2) * 66 + n] = pb[i].z;
            Bb[(4 * kq + 3) * 66 + n] = pb[i].w;
        }
    };

    unsigned long long acc2[8][4] = {};   // [row i][col-pair p]

    ldgB(0);
    issueA(0, 0);
    stsB(0);
    cp_wait0();
    __syncthreads();

    for (int kt = 0; kt < kiters; kt++) {
        const int buf = kt & 1;
        if (kt + 1 < kiters) { issueA(kt + 1, buf ^ 1); ldgB(kt + 1); }

        const float4* Ab = As4 + buf * A_F4;
        const float*  Bb = BPf + buf * B_F;
#pragma unroll
        for (int kq = 0; kq < 8; kq++) {
            float4 a4[8];
#pragma unroll
            for (int i = 0; i < 8; i++) a4[i] = Ab[kq * 129 + mr + (i << 4)];
#pragma unroll
            for (int dk = 0; dk < 4; dk++) {
                const int k = (kq << 2) + dk;
                unsigned long long b2[4];
#pragma unroll
                for (int p = 0; p < 4; p++)
                    b2[p] = *(const unsigned long long*)&Bb[k * 66 + ((ng + (p << 3)) << 1)];
                unsigned long long ad[8];
#pragma unroll
                for (int i = 0; i < 8; i++) {
                    const float av = (dk == 0) ? a4[i].x : (dk == 1) ? a4[i].y
                                   : (dk == 2) ? a4[i].z : a4[i].w;
                    ad[i] = dup2(av);
                }
#pragma unroll
                for (int i = 0; i < 8; i++)
#pragma unroll
                    for (int p = 0; p < 4; p++)
                        fma2(acc2[i][p], ad[i], b2[p]);
            }
        }
        if (kt + 1 < kiters) {
            __syncthreads();
            stsB(buf ^ 1);
            cp_wait0();
            __syncthreads();
        }
    }

    __syncthreads();
    float* Cs = (float*)gsm4;      // 128 x 68
#pragma unroll
    for (int i = 0; i < 8; i++)
#pragma unroll
        for (int p = 0; p < 4; p++) {
            const int col = (ng + (p << 3)) << 1;
            *(unsigned long long*)&Cs[(mr + (i << 4)) * 68 + col] = acc2[i][p];
        }
    __syncthreads();
#pragma unroll
    for (int i = 0; i < 16; i++) {
        const int f = t + (i << 7);
        const int m = f >> 4, q = f & 15;
        *(float4*)&Cp[(m0 + m) * 512 + n0 + (q << 2)] =
            *(const float4*)&Cs[m * 68 + (q << 2)];
    }
}

// qkv partials: grid (8, 4, 12); z = mat*4 + kslice (K=128 per slice)
__global__ void __launch_bounds__(128, 3) qkv_part(const float* __restrict__ X,
                                                   const float* __restrict__ Wq,
                                                   const float* __restrict__ Wk,
                                                   const float* __restrict__ Wv)
{
    const int z = blockIdx.z;
    const int mat = z >> 2, ks = z & 3;
    const float* B = (mat == 0) ? Wq : (mat == 1) ? Wk : Wv;
    gemm128x64(X, B, g_qkvp + z * (NSEQ * DMODEL), ks << 7, 4);
}

// reduce 4 qkv partials -> g_Q/g_K/g_V.  grid 768 x 256
__global__ void __launch_bounds__(256) reduce_qkv()
{
    const int idx = blockIdx.x * 256 + threadIdx.x;
    const int mat = idx >> 16, r = idx & 0xFFFF;
    const float4* p = (const float4*)g_qkvp;
    float4 a = p[(mat * 4 + 0) * 65536 + r];
    float4 b = p[(mat * 4 + 1) * 65536 + r];
    float4 c = p[(mat * 4 + 2) * 65536 + r];
    float4 d = p[(mat * 4 + 3) * 65536 + r];
    float4 s = {a.x + b.x + c.x + d.x, a.y + b.y + c.y + d.y,
                a.z + b.z + c.z + d.z, a.w + b.w + c.w + d.w};
    float4* o = (mat == 0) ? (float4*)g_Q : (mat == 1) ? (float4*)g_K : (float4*)g_V;
    o[r] = s;
}

// ---------------------------------------------------------------------------
// tf32x3 GEMM (flip-free out-projection only), split-K
// ---------------------------------------------------------------------------
__device__ __forceinline__ uint32_t f2tf32(float x) {
    uint32_t r;
    asm("cvt.rna.tf32.f32 %0, %1;" : "=r"(r) : "f"(x));
    return r;
}
__device__ __forceinline__ void split_tf32(float x, uint32_t& h, uint32_t& l) {
    h = f2tf32(x);
    l = f2tf32(x - __uint_as_float(h));
}
__device__ __forceinline__ void mma_tf32(float c[4], const uint32_t a[4],
                                         const uint32_t b[2]) {
    asm volatile(
        "mma.sync.aligned.m16n8k8.row.col.f32.tf32.tf32.f32 "
        "{%0,%1,%2,%3}, {%4,%5,%6,%7}, {%8,%9}, {%0,%1,%2,%3};"
        : "+f"(c[0]), "+f"(c[1]), "+f"(c[2]), "+f"(c[3])
        : "r"(a[0]), "r"(a[1]), "r"(a[2]), "r"(a[3]), "r"(b[0]), "r"(b[1]));
}

#define AH_OFF 0
#define AL_OFF 9216
#define BH_OFF 18432
#define BL_OFF 23040
#define MMA_SMEM_BYTES ((BL_OFF + 2 * 2304) * 4)

__device__ __forceinline__ void gemm_tf32x3(const float* __restrict__ A,
                                            const float* __restrict__ B,
                                            float* __restrict__ C,
                                            int kbase, int kiters)
{
    extern __shared__ uint32_t gsm[];
    uint32_t* AH = gsm + AH_OFF;
    uint32_t* AL = gsm + AL_OFF;
    uint32_t* BH = gsm + BH_OFF;
    uint32_t* BL = gsm + BL_OFF;

    const int t    = threadIdx.x;
    const int wid  = t >> 5, lane = t & 31;
    const int wm   = (wid >> 1) << 5;
    const int wn   = (wid & 1) << 5;
    const int G    = lane >> 2;
    const int tg   = lane & 3;
    const int m0   = blockIdx.y * 128;
    const int n0   = blockIdx.x * 64;

    float4 pa[4], pb[2];

    auto ldg_chunk = [&](int k0) {
#pragma unroll
        for (int i = 0; i < 4; i++) {
            const int f = t + (i << 8);
            pa[i] = *(const float4*)&A[(m0 + (f >> 3)) * 512 + k0 + ((f & 7) << 2)];
        }
#pragma unroll
        for (int i = 0; i < 2; i++) {
            const int f = t + (i << 8);
            pb[i] = *(const float4*)&B[(n0 + (f >> 3)) * 512 + k0 + ((f & 7) << 2)];
        }
    };
    auto sts_chunk = [&](int buf) {
#pragma unroll
        for (int i = 0; i < 4; i++) {
            const int f = t + (i << 8);
            const int m = f >> 3, kq = (f & 7) << 2;
            uint4 h4, l4;
            split_tf32(pa[i].x, h4.x, l4.x);
            split_tf32(pa[i].y, h4.y, l4.y);
            split_tf32(pa[i].z, h4.z, l4.z);
            split_tf32(pa[i].w, h4.w, l4.w);
            *(uint4*)&AH[buf * 4608 + m * 36 + kq] = h4;
            *(uint4*)&AL[buf * 4608 + m * 36 + kq] = l4;
        }
#pragma unroll
        for (int i = 0; i < 2; i++) {
            const int f = t + (i << 8);
            const int n = f >> 3, kq = (f & 7) << 2;
            uint4 h4, l4;
            split_tf32(pb[i].x, h4.x, l4.x);
            split_tf32(pb[i].y, h4.y, l4.y);
            split_tf32(pb[i].z, h4.z, l4.z);
            split_tf32(pb[i].w, h4.w, l4.w);
            *(uint4*)&BH[buf * 2304 + n * 36 + kq] = h4;
            *(uint4*)&BL[buf * 2304 + n * 36 + kq] = l4;
        }
    };

    float c[2][4][4] = {};

    ldg_chunk(kbase);
    sts_chunk(0);
    __syncthreads();

    for (int kt = 0; kt < kiters; kt++) {
        const int buf = kt & 1;
        if (kt + 1 < kiters) ldg_chunk(kbase + ((kt + 1) << 5));

        const uint32_t* ah = AH + buf * 4608;
        const uint32_t* al = AL + buf * 4608;
        const uint32_t* bh = BH + buf * 2304;
        const uint32_t* bl = BL + buf * 2304;
#pragma unroll
        for (int kk = 0; kk < 4; kk++) {
            const int kb = kk << 3;
            uint32_t aH[2][4], aL[2][4];
#pragma unroll
            for (int mt = 0; mt < 2; mt++) {
                const int base = (wm + (mt << 4) + G) * 36 + kb + tg;
                aH[mt][0] = ah[base];
                aH[mt][1] = ah[base + 8 * 36];
                aH[mt][2] = ah[base + 4];
                aH[mt][3] = ah[base + 8 * 36 + 4];
                aL[mt][0] = al[base];
                aL[mt][1] = al[base + 8 * 36];
                aL[mt][2] = al[base + 4];
                aL[mt][3] = al[base + 8 * 36 + 4];
            }
#pragma unroll
            for (int nt = 0; nt < 4; nt++) {
                const int bbase = (wn + (nt << 3) + G) * 36 + kb + tg;
                uint32_t bHf[2] = {bh[bbase], bh[bbase + 4]};
                uint32_t bLf[2] = {bl[bbase], bl[bbase + 4]};
#pragma unroll
                for (int mt = 0; mt < 2; mt++) {
                    mma_tf32(c[mt][nt], aH[mt], bHf);
                    mma_tf32(c[mt][nt], aH[mt], bLf);
                    mma_tf32(c[mt][nt], aL[mt], bHf);
                }
            }
        }
        if (kt + 1 < kiters) {
            __syncthreads();
            sts_chunk(buf ^ 1);
            __syncthreads();
        }
    }

#pragma unroll
    for (int mt = 0; mt < 2; mt++) {
        const int r0 = m0 + wm + (mt << 4) + G;
#pragma unroll
        for (int nt = 0; nt < 4; nt++) {
            const int col = n0 + wn + (nt << 3) + (tg << 1);
            *(float2*)&C[r0 * 512 + col]       = make_float2(c[mt][nt][0], c[mt][nt][1]);
            *(float2*)&C[(r0 + 8) * 512 + col] = make_float2(c[mt][nt][2], c[mt][nt][3]);
        }
    }
}

// out partials: grid (8, 4, 8); z = kslice (K=64, 2 BK iters)
__global__ void __launch_bounds__(256) out_part(const float* __restrict__ Wo)
{
    const int ks = blockIdx.z;
    gemm_tf32x3(g_ctx, Wo, g_outp + ks * (NSEQ * DMODEL), ks << 6, 2);
}

// reduce 8 out partials -> d_out.  grid 256 x 256
__global__ void __launch_bounds__(256) reduce_out(float* __restrict__ out)
{
    const int r = blockIdx.x * 256 + threadIdx.x;
    const float4* p = (const float4*)g_outp;
    float4 s = {0.f, 0.f, 0.f, 0.f};
#pragma unroll
    for (int k = 0; k < 8; k++) {
        float4 v = p[k * 65536 + r];
        s.x += v.x; s.y += v.y; s.z += v.z; s.w += v.w;
    }
    ((float4*)out)[r] = s;
}

// ---------------------------------------------------------------------------
// Fused attention v3: block = (16 rows, 1 head), 256 thr, grid (32,8).
// Scores live in REGISTERS (no ScT smem); K chunks cp.async double-buffered.
// smem floats: KC[2] f4[16*129] each (0 / 8256), Q4 f4[16*17] (16512),
//              L u32[16*52] (17600).  Total 73728 B -> occ 3.
// ---------------------------------------------------------------------------
#define KCB_F   8256
#define AQ_OFF  16512
#define AL_OFF2 17600
#define ATTN_SMEM_BYTES ((AL_OFF2 + 16 * 52) * 4)

__global__ void __launch_bounds__(256, 3) attn_kernel()
{
    extern __shared__ float sm[];
    float4*   Q4 = (float4*)(sm + AQ_OFF);
    uint32_t* L  = (uint32_t*)(sm + AL_OFF2);

    const int h    = blockIdx.y;
    const int row0 = blockIdx.x * 16;
    const int t    = threadIdx.x;
    const int warp = t >> 5, lane = t & 31;
    const int rw   = warp << 1;

    const uint32_t sKC = (uint32_t)__cvta_generic_to_shared(sm);

    // issue K chunk ch into buffer buf via cp.async (16B contiguous segments)
    auto issue_k = [&](int ch, int buf) {
#pragma unroll
        for (int i = 0; i < 8; i++) {
            const int f = t + (i << 8);
            const int col = f >> 4, d4 = f & 15;
            cp16(sKC + (uint32_t)((buf * 2064 + d4 * 129 + col) << 4),
                 &g_K[(ch * 128 + col) * DMODEL + h * DH + (d4 << 2)]);
        }
        cp_commit();
    };

    // ---- prologue: Q tile + K chunk 0 ----
    {
        const int r = t >> 4, d4 = t & 15;
        Q4[d4 * 17 + r] = *(const float4*)&g_Q[(row0 + r) * DMODEL + h * DH + (d4 << 2)];
    }
    issue_k(0, 0);
    cp_wait0();
    __syncthreads();

    // ---- phase 1: scores -> registers v0/v1 (v[4*ch + c] = col lane+32c) ----
    float v0[16], v1[16];
#pragma unroll
    for (int ch = 0; ch < 4; ch++) {
        if (ch < 3) issue_k(ch + 1, (ch + 1) & 1);
        const float4* KC = (const float4*)sm + (ch & 1) * 2064;
        float acc0[4] = {}, acc1[4] = {};
#pragma unroll 4
        for (int d4 = 0; d4 < 16; d4++) {
            const float4 q0 = Q4[d4 * 17 + rw];
            const float4 q1 = Q4[d4 * 17 + rw + 1];
#pragma unroll
            for (int c = 0; c < 4; c++) {
                const float4 k4 = KC[d4 * 129 + lane + (c << 5)];
                float s0 = acc0[c], s1 = acc1[c];
                s0 = fmaf(q0.x, k4.x, s0); s1 = fmaf(q1.x, k4.x, s1);
                s0 = fmaf(q0.y, k4.y, s0); s1 = fmaf(q1.y, k4.y, s1);
                s0 = fmaf(q0.z, k4.z, s0); s1 = fmaf(q1.z, k4.z, s1);
                s0 = fmaf(q0.w, k4.w, s0); s1 = fmaf(q1.w, k4.w, s1);
                acc0[c] = s0; acc1[c] = s1;
            }
        }
#pragma unroll
        for (int c = 0; c < 4; c++) {
            v0[(ch << 2) + c] = fabsf(acc0[c]) * SCALE;
            v1[(ch << 2) + c] = fabsf(acc1[c]) * SCALE;
        }
        if (ch < 3) {
            cp_wait0();
            __syncthreads();
        }
    }

    // ---- phase 2: top-51 -> compacted normalized (w, idx) lists ----
    const unsigned ltmask = (1u << lane) - 1u;
    auto topk = [&](float (&v)[16], uint32_t* Lr) {
        unsigned u[16];
        float ssum = 0.f;
#pragma unroll
        for (int i = 0; i < 16; i++) {
            u[i] = __float_as_uint(v[i]);
            ssum += v[i];
        }
        unsigned lo = 0u, hi = 0x7F800000u;
        while (lo < hi) {
            unsigned mid = lo + ((hi - lo + 1u) >> 1);
            int cnt = 0;
#pragma unroll
            for (int i = 0; i < 16; i++) cnt += (u[i] >= mid);
            cnt = __reduce_add_sync(0xffffffffu, cnt);
            if (cnt >= KTOP) lo = mid; else hi = mid - 1u;
        }
        const unsigned T = lo;
        int   cgt  = 0;
        float tsum = 0.f;
#pragma unroll
        for (int i = 0; i < 16; i++)
            if (u[i] > T) { cgt++; tsum += v[i]; }
        cgt = __reduce_add_sync(0xffffffffu, cgt);
#pragma unroll
        for (int o = 16; o; o >>= 1) {
            tsum += __shfl_xor_sync(0xffffffffu, tsum, o);
            ssum += __shfl_xor_sync(0xffffffffu, ssum, o);
        }
        const float Tf = __uint_as_float(T);
        tsum += (float)(KTOP - cgt) * Tf;
        const float inv = 1.0f / (tsum + 1e-8f * (ssum + 1e-8f));

        int base = 0;
        int brem = KTOP - cgt;
#pragma unroll
        for (int i = 0; i < 16; i++) {
            const bool gt = (u[i] > T);
            const bool eq = (u[i] == T);
            const unsigned eqm = __ballot_sync(0xffffffffu, eq);
            const bool teq = eq && (__popc(eqm & ltmask) < brem);
            const unsigned selm = __ballot_sync(0xffffffffu, gt || teq);
            if (gt || teq) {
                const int pos = base + __popc(selm & ltmask);
                const float w = v[i] * inv;
                Lr[pos] = (__float_as_uint(w) & ~511u) | (unsigned)(lane + 32 * i);
            }
            base += __popc(selm);
            const int nties = __popc(eqm);
            brem -= (nties < brem) ? nties : brem;
        }
    };
    topk(v0, L + rw * 52);
    topk(v1, L + (rw + 1) * 52);
    __syncwarp();

    // ---- phase 3: fused gather for both rows (6 loads in flight) ----
    {
        const uint32_t* L0 = L + rw * 52;
        const uint32_t* L1 = L0 + 52;
        float2 a0[3] = {{0.f,0.f},{0.f,0.f},{0.f,0.f}};
        float2 a1[3] = {{0.f,0.f},{0.f,0.f},{0.f,0.f}};
#pragma unroll 3
        for (int e = 0; e < KTOP; e++) {
            const uint32_t b0 = L0[e], b1 = L1[e];
            const float w0 = __uint_as_float(b0 & ~511u);
            const float w1 = __uint_as_float(b1 & ~511u);
            const float2 va = *(const float2*)&g_V[(b0 & 511u) * DMODEL + h * DH + (lane << 1)];
            const float2 vb = *(const float2*)&g_V[(b1 & 511u) * DMODEL + h * DH + (lane << 1)];
            float2& x0 = a0[e % 3];
            float2& x1 = a1[e % 3];
            x0.x = fmaf(w0, va.x, x0.x); x0.y = fmaf(w0, va.y, x0.y);
            x1.x = fmaf(w1, vb.x, x1.x); x1.y = fmaf(w1, vb.y, x1.y);
        }
        float2 o0 = {a0[0].x + a0[1].x + a0[2].x, a0[0].y + a0[1].y + a0[2].y};
        float2 o1 = {a1[0].x + a1[1].x + a1[2].x, a1[0].y + a1[1].y + a1[2].y};
        *(float2*)&g_ctx[(row0 + rw) * DMODEL + h * DH + (lane << 1)]     = o0;
        *(float2*)&g_ctx[(row0 + rw + 1) * DMODEL + h * DH + (lane << 1)] = o1;
    }
}

// ---------------------------------------------------------------------------
extern "C" void kernel_launch(void* const* d_in, const int* in_sizes, int n_in,
                              void* d_out, int out_size)
{
    const float* x  = (const float*)d_in[0];
    const float* Wq = (const float*)d_in[1];
    const float* Wk = (const float*)d_in[2];
    const float* Wv = (const float*)d_in[3];
    const float* Wo = (const float*)d_in[4];
    float* out = (float*)d_out;

    cudaFuncSetAttribute(qkv_part, cudaFuncAttributeMaxDynamicSharedMemorySize, GEMM_SMEM_BYTES);
    cudaFuncSetAttribute(out_part, cudaFuncAttributeMaxDynamicSharedMemorySize, MMA_SMEM_BYTES);
    cudaFuncSetAttribute(attn_kernel, cudaFuncAttributeMaxDynamicSharedMemorySize, ATTN_SMEM_BYTES);

    qkv_part<<<dim3(8, 4, 12), 128, GEMM_SMEM_BYTES>>>(x, Wq, Wk, Wv);
    reduce_qkv<<<768, 256>>>();
    attn_kernel<<<dim3(32, 8), 256, ATTN_SMEM_BYTES>>>();
    out_part<<<dim3(8, 4, 8), 256, MMA_SMEM_BYTES>>>(Wo);
    reduce_out<<<256, 256>>>(out);
}

// round 12
// speedup vs baseline: 1.1381x; 1.1381x over previous
#include <cuda_runtime.h>
#include <cstdint>

#define NSEQ 512
#define DMODEL 512
#define DH 64
#define NH 8
#define KTOP 51
#define SCALE 2.8284271247461903f   // dh^0.25

// scratch (allocation-free rule: __device__ globals)
__device__ float g_Q[NSEQ * DMODEL];
__device__ float g_K[NSEQ * DMODEL];
__device__ float g_V[NSEQ * DMODEL];
__device__ float g_ctx[NSEQ * DMODEL];
__device__ float g_qkvp[12 * NSEQ * DMODEL];  // qkv split-K partials
__device__ float g_outp[8 * NSEQ * DMODEL];   // out split-K partials

// ---------------------------------------------------------------------------
// cp.async + f32x2 helpers
// ---------------------------------------------------------------------------
__device__ __forceinline__ void cp16(uint32_t dst, const void* src) {
    asm volatile("cp.async.cg.shared.global [%0], [%1], 16;" :: "r"(dst), "l"(src));
}
__device__ __forceinline__ void cp_commit() { asm volatile("cp.async.commit_group;"); }
__device__ __forceinline__ void cp_wait0()  { asm volatile("cp.async.wait_group 0;"); }

__device__ __forceinline__ unsigned long long dup2(float x) {
    unsigned long long r;
    asm("mov.b64 %0, {%1, %1};" : "=l"(r) : "r"(__float_as_uint(x)));
    return r;
}
__device__ __forceinline__ void fma2(unsigned long long& d,
                                     unsigned long long a, unsigned long long b) {
    asm("fma.rn.f32x2 %0, %1, %2, %0;" : "+l"(d) : "l"(a), "l"(b));
}

// ---------------------------------------------------------------------------
// fp32 GEMM partial with packed f32x2 (bit-identical to scalar FFMA):
// Cp(128x64) = A * B^T over one K slice. 128 threads, micro 8 rows x 4 col-pairs.
// ---------------------------------------------------------------------------
#define A_F4   1032                      // 8*129 per buf
#define B_F    (32 * 66)                 // per buf
#define GEMM_SMEM_BYTES (2 * A_F4 * 16 + 2 * B_F * 4)

__device__ __forceinline__ void gemm128x64(const float* __restrict__ A,
                                           const float* __restrict__ B,
                                           float* __restrict__ Cp,
                                           int kbase, int kiters)
{
    extern __shared__ float4 gsm4[];
    float4* As4 = gsm4;                         // 2 * A_F4
    float*  BPf = (float*)(gsm4 + 2 * A_F4);    // 2 * B_F
    const int t  = threadIdx.x;
    const int mr = t & 15;              // rows mr + 16*i
    const int ng = t >> 4;              // col-pairs 2*(ng+8p)
    const int m0 = blockIdx.y * 128;
    const int n0 = blockIdx.x * 64;

    const uint32_t sA = (uint32_t)__cvta_generic_to_shared(As4);

    float4 pb[4];

    auto issueA = [&](int kit, int buf) {
        const int k0 = kbase + (kit << 5);
#pragma unroll
        for (int i = 0; i < 8; i++) {
            const int f = t + (i << 7);
            const int m = f >> 3, kq = f & 7;
            cp16(sA + (uint32_t)((buf * A_F4 + kq * 129 + m) << 4),
                 &A[(m0 + m) * 512 + k0 + (kq << 2)]);
        }
        cp_commit();
    };
    auto ldgB = [&](int kit) {
        const int k0 = kbase + (kit << 5);
#pragma unroll
        for (int i = 0; i < 4; i++) {
            const int f = t + (i << 7);
            pb[i] = *(const float4*)&B[(n0 + (f >> 3)) * 512 + k0 + ((f & 7) << 2)];
        }
    };
    auto stsB = [&](int buf) {
        float* Bb = BPf + buf * B_F;
#pragma unroll
        for (int i = 0; i < 4; i++) {
            const int f = t + (i << 7);
            const int n = f >> 3, kq = f & 7;
            Bb[(4 * kq + 0) * 66 + n] = pb[i].x;
            Bb[(4 * kq + 1) * 66 + n] = pb[i].y;
            Bb[(4 * kq + 2) * 66 + n] = pb[i].z;
            Bb[(4 * kq + 3) * 66 + n] = pb[i].w;
        }
    };

    unsigned long long acc2[8][4] = {};   // [row i][col-pair p]

    ldgB(0);
    issueA(0, 0);
    stsB(0);
    cp_wait0();
    __syncthreads();

    for (int kt = 0; kt < kiters; kt++) {
        const int buf = kt & 1;
        if (kt + 1 < kiters) { issueA(kt + 1, buf ^ 1); ldgB(kt + 1); }

        const float4* Ab = As4 + buf * A_F4;
        const float*  Bb = BPf + buf * B_F;
#pragma unroll
        for (int kq = 0; kq < 8; kq++) {
            float4 a4[8];
#pragma unroll
            for (int i = 0; i < 8; i++) a4[i] = Ab[kq * 129 + mr + (i << 4)];
#pragma unroll
            for (int dk = 0; dk < 4; dk++) {
                const int k = (kq << 2) + dk;
                unsigned long long b2[4];
#pragma unroll
                for (int p = 0; p < 4; p++)
                    b2[p] = *(const unsigned long long*)&Bb[k * 66 + ((ng + (p << 3)) << 1)];
                unsigned long long ad[8];
#pragma unroll
                for (int i = 0; i < 8; i++) {
                    const float av = (dk == 0) ? a4[i].x : (dk == 1) ? a4[i].y
                                   : (dk == 2) ? a4[i].z : a4[i].w;
                    ad[i] = dup2(av);
                }
#pragma unroll
                for (int i = 0; i < 8; i++)
#pragma unroll
                    for (int p = 0; p < 4; p++)
                        fma2(acc2[i][p], ad[i], b2[p]);
            }
        }
        if (kt + 1 < kiters) {
            __syncthreads();
            stsB(buf ^ 1);
            cp_wait0();
            __syncthreads();
        }
    }

    __syncthreads();
    float* Cs = (float*)gsm4;      // 128 x 68
#pragma unroll
    for (int i = 0; i < 8; i++)
#pragma unroll
        for (int p = 0; p < 4; p++) {
            const int col = (ng + (p << 3)) << 1;
            *(unsigned long long*)&Cs[(mr + (i << 4)) * 68 + col] = acc2[i][p];
        }
    __syncthreads();
#pragma unroll
    for (int i = 0; i < 16; i++) {
        const int f = t + (i << 7);
        const int m = f >> 4, q = f & 15;
        *(float4*)&Cp[(m0 + m) * 512 + n0 + (q << 2)] =
            *(const float4*)&Cs[m * 68 + (q << 2)];
    }
}

// qkv partials: grid (8, 4, 12); z = mat*4 + kslice (K=128 per slice)
__global__ void __launch_bounds__(128, 3) qkv_part(const float* __restrict__ X,
                                                   const float* __restrict__ Wq,
                                                   const float* __restrict__ Wk,
                                                   const float* __restrict__ Wv)
{
    const int z = blockIdx.z;
    const int mat = z >> 2, ks = z & 3;
    const float* B = (mat == 0) ? Wq : (mat == 1) ? Wk : Wv;
    gemm128x64(X, B, g_qkvp + z * (NSEQ * DMODEL), ks << 7, 4);
}

// reduce 4 qkv partials -> g_Q/g_K/g_V.  grid 768 x 256
__global__ void __launch_bounds__(256) reduce_qkv()
{
    const int idx = blockIdx.x * 256 + threadIdx.x;
    const int mat = idx >> 16, r = idx & 0xFFFF;
    const float4* p = (const float4*)g_qkvp;
    float4 a = p[(mat * 4 + 0) * 65536 + r];
    float4 b = p[(mat * 4 + 1) * 65536 + r];
    float4 c = p[(mat * 4 + 2) * 65536 + r];
    float4 d = p[(mat * 4 + 3) * 65536 + r];
    float4 s = {a.x + b.x + c.x + d.x, a.y + b.y + c.y + d.y,
                a.z + b.z + c.z + d.z, a.w + b.w + c.w + d.w};
    float4* o = (mat == 0) ? (float4*)g_Q : (mat == 1) ? (float4*)g_K : (float4*)g_V;
    o[r] = s;
}

// ---------------------------------------------------------------------------
// tf32x3 GEMM (flip-free out-projection only), split-K
// ---------------------------------------------------------------------------
__device__ __forceinline__ uint32_t f2tf32(float x) {
    uint32_t r;
    asm("cvt.rna.tf32.f32 %0, %1;" : "=r"(r) : "f"(x));
    return r;
}
__device__ __forceinline__ void split_tf32(float x, uint32_t& h, uint32_t& l) {
    h = f2tf32(x);
    l = f2tf32(x - __uint_as_float(h));
}
__device__ __forceinline__ void mma_tf32(float c[4], const uint32_t a[4],
                                         const uint32_t b[2]) {
    asm volatile(
        "mma.sync.aligned.m16n8k8.row.col.f32.tf32.tf32.f32 "
        "{%0,%1,%2,%3}, {%4,%5,%6,%7}, {%8,%9}, {%0,%1,%2,%3};"
        : "+f"(c[0]), "+f"(c[1]), "+f"(c[2]), "+f"(c[3])
        : "r"(a[0]), "r"(a[1]), "r"(a[2]), "r"(a[3]), "r"(b[0]), "r"(b[1]));
}

#define AH_OFF 0
#define AL_OFF 9216
#define BH_OFF 18432
#define BL_OFF 23040
#define MMA_SMEM_BYTES ((BL_OFF + 2 * 2304) * 4)

__device__ __forceinline__ void gemm_tf32x3(const float* __restrict__ A,
                                            const float* __restrict__ B,
                                            float* __restrict__ C,
                                            int kbase, int kiters)
{
    extern __shared__ uint32_t gsm[];
    uint32_t* AH = gsm + AH_OFF;
    uint32_t* AL = gsm + AL_OFF;
    uint32_t* BH = gsm + BH_OFF;
    uint32_t* BL = gsm + BL_OFF;

    const int t    = threadIdx.x;
    const int wid  = t >> 5, lane = t & 31;
    const int wm   = (wid >> 1) << 5;
    const int wn   = (wid & 1) << 5;
    const int G    = lane >> 2;
    const int tg   = lane & 3;
    const int m0   = blockIdx.y * 128;
    const int n0   = blockIdx.x * 64;

    float4 pa[4], pb[2];

    auto ldg_chunk = [&](int k0) {
#pragma unroll
        for (int i = 0; i < 4; i++) {
            const int f = t + (i << 8);
            pa[i] = *(const float4*)&A[(m0 + (f >> 3)) * 512 + k0 + ((f & 7) << 2)];
        }
#pragma unroll
        for (int i = 0; i < 2; i++) {
            const int f = t + (i << 8);
            pb[i] = *(const float4*)&B[(n0 + (f >> 3)) * 512 + k0 + ((f & 7) << 2)];
        }
    };
    auto sts_chunk = [&](int buf) {
#pragma unroll
        for (int i = 0; i < 4; i++) {
            const int f = t + (i << 8);
            const int m = f >> 3, kq = (f & 7) << 2;
            uint4 h4, l4;
            split_tf32(pa[i].x, h4.x, l4.x);
            split_tf32(pa[i].y, h4.y, l4.y);
            split_tf32(pa[i].z, h4.z, l4.z);
            split_tf32(pa[i].w, h4.w, l4.w);
            *(uint4*)&AH[buf * 4608 + m * 36 + kq] = h4;
            *(uint4*)&AL[buf * 4608 + m * 36 + kq] = l4;
        }
#pragma unroll
        for (int i = 0; i < 2; i++) {
            const int f = t + (i << 8);
            const int n = f >> 3, kq = (f & 7) << 2;
            uint4 h4, l4;
            split_tf32(pb[i].x, h4.x, l4.x);
            split_tf32(pb[i].y, h4.y, l4.y);
            split_tf32(pb[i].z, h4.z, l4.z);
            split_tf32(pb[i].w, h4.w, l4.w);
            *(uint4*)&BH[buf * 2304 + n * 36 + kq] = h4;
            *(uint4*)&BL[buf * 2304 + n * 36 + kq] = l4;
        }
    };

    float c[2][4][4] = {};

    ldg_chunk(kbase);
    sts_chunk(0);
    __syncthreads();

    for (int kt = 0; kt < kiters; kt++) {
        const int buf = kt & 1;
        if (kt + 1 < kiters) ldg_chunk(kbase + ((kt + 1) << 5));

        const uint32_t* ah = AH + buf * 4608;
        const uint32_t* al = AL + buf * 4608;
        const uint32_t* bh = BH + buf * 2304;
        const uint32_t* bl = BL + buf * 2304;
#pragma unroll
        for (int kk = 0; kk < 4; kk++) {
            const int kb = kk << 3;
            uint32_t aH[2][4], aL[2][4];
#pragma unroll
            for (int mt = 0; mt < 2; mt++) {
                const int base = (wm + (mt << 4) + G) * 36 + kb + tg;
                aH[mt][0] = ah[base];
                aH[mt][1] = ah[base + 8 * 36];
                aH[mt][2] = ah[base + 4];
                aH[mt][3] = ah[base + 8 * 36 + 4];
                aL[mt][0] = al[base];
                aL[mt][1] = al[base + 8 * 36];
                aL[mt][2] = al[base + 4];
                aL[mt][3] = al[base + 8 * 36 + 4];
            }
#pragma unroll
            for (int nt = 0; nt < 4; nt++) {
                const int bbase = (wn + (nt << 3) + G) * 36 + kb + tg;
                uint32_t bHf[2] = {bh[bbase], bh[bbase + 4]};
                uint32_t bLf[2] = {bl[bbase], bl[bbase + 4]};
#pragma unroll
                for (int mt = 0; mt < 2; mt++) {
                    mma_tf32(c[mt][nt], aH[mt], bHf);
                    mma_tf32(c[mt][nt], aH[mt], bLf);
                    mma_tf32(c[mt][nt], aL[mt], bHf);
                }
            }
        }
        if (kt + 1 < kiters) {
            __syncthreads();
            sts_chunk(buf ^ 1);
            __syncthreads();
        }
    }

#pragma unroll
    for (int mt = 0; mt < 2; mt++) {
        const int r0 = m0 + wm + (mt << 4) + G;
#pragma unroll
        for (int nt = 0; nt < 4; nt++) {
            const int col = n0 + wn + (nt << 3) + (tg << 1);
            *(float2*)&C[r0 * 512 + col]       = make_float2(c[mt][nt][0], c[mt][nt][1]);
            *(float2*)&C[(r0 + 8) * 512 + col] = make_float2(c[mt][nt][2], c[mt][nt][3]);
        }
    }
}

// out partials: grid (8, 4, 8); z = kslice (K=64, 2 BK iters)
__global__ void __launch_bounds__(256) out_part(const float* __restrict__ Wo)
{
    const int ks = blockIdx.z;
    gemm_tf32x3(g_ctx, Wo, g_outp + ks * (NSEQ * DMODEL), ks << 6, 2);
}

// reduce 8 out partials -> d_out.  grid 256 x 256
__global__ void __launch_bounds__(256) reduce_out(float* __restrict__ out)
{
    const int r = blockIdx.x * 256 + threadIdx.x;
    const float4* p = (const float4*)g_outp;
    float4 s = {0.f, 0.f, 0.f, 0.f};
#pragma unroll
    for (int k = 0; k < 8; k++) {
        float4 v = p[k * 65536 + r];
        s.x += v.x; s.y += v.y; s.z += v.z; s.w += v.w;
    }
    ((float4*)out)[r] = s;
}

// ---------------------------------------------------------------------------
// Fused attention (round-10 baseline + interleaved dual-row top-k search):
// block = (16 rows, 1 head), 256 thr, grid (32,8), occ 3.
// Warp w owns rows {2w,2w+1}; phases 2+3 barrier-free.
// ---------------------------------------------------------------------------
#define SCT_OFF 0
#define AQ4_OFF 8704
#define KC_OFF  9792
#define AL_OFF2 18048
#define ATTN_SMEM_BYTES ((AL_OFF2 + 16 * 52) * 4)

__global__ void __launch_bounds__(256, 3) attn_kernel()
{
    extern __shared__ float sm[];
    float*    ScT = sm + SCT_OFF;
    float4*   Q4  = (float4*)(sm + AQ4_OFF);
    float4*   KC  = (float4*)(sm + KC_OFF);
    uint32_t* L   = (uint32_t*)(sm + AL_OFF2);

    const int h    = blockIdx.y;
    const int row0 = blockIdx.x * 16;
    const int t    = threadIdx.x;
    const int warp = t >> 5, lane = t & 31;

    // ---- load Q + K chunk 0 ----
    {
        const int r = t >> 4, d4 = t & 15;
        Q4[d4 * 17 + r] = *(const float4*)&g_Q[(row0 + r) * DMODEL + h * DH + (d4 << 2)];
    }
#pragma unroll
    for (int i = 0; i < 8; i++) {
        const int f = t + (i << 8);
        KC[(f & 15) * 129 + (f >> 4)] =
            *(const float4*)&g_K[(f >> 4) * DMODEL + h * DH + ((f & 15) << 2)];
    }
    __syncthreads();

    // ---- phase 1: warp w computes rows {2w, 2w+1} ----
    const int rw = warp << 1;
    for (int ch = 0; ch < 4; ch++) {
        float acc0[4] = {}, acc1[4] = {};
#pragma unroll 4
        for (int d4 = 0; d4 < 16; d4++) {
            const float4 q0 = Q4[d4 * 17 + rw];
            const float4 q1 = Q4[d4 * 17 + rw + 1];
#pragma unroll
            for (int c = 0; c < 4; c++) {
                const float4 k4 = KC[d4 * 129 + lane + (c << 5)];
                float s0 = acc0[c], s1 = acc1[c];
                s0 = fmaf(q0.x, k4.x, s0); s1 = fmaf(q1.x, k4.x, s1);
                s0 = fmaf(q0.y, k4.y, s0); s1 = fmaf(q1.y, k4.y, s1);
                s0 = fmaf(q0.z, k4.z, s0); s1 = fmaf(q1.z, k4.z, s1);
                s0 = fmaf(q0.w, k4.w, s0); s1 = fmaf(q1.w, k4.w, s1);
                acc0[c] = s0; acc1[c] = s1;
            }
        }
#pragma unroll
        for (int c = 0; c < 4; c++) {
            const int j = (ch << 7) + lane + (c << 5);
            ScT[j * 17 + rw]     = fabsf(acc0[c]) * SCALE;
            ScT[j * 17 + rw + 1] = fabsf(acc1[c]) * SCALE;
        }
        if (ch < 3) {
            __syncthreads();
#pragma unroll
            for (int i = 0; i < 8; i++) {
                const int f = t + (i << 8);
                KC[(f & 15) * 129 + (f >> 4)] =
                    *(const float4*)&g_K[((ch + 1) * 128 + (f >> 4)) * DMODEL + h * DH + ((f & 15) << 2)];
            }
            __syncthreads();
        }
    }
    __syncwarp();

    // ---- phase 2: interleaved dual-row top-51 search + compaction ----
    const unsigned ltmask = (1u << lane) - 1u;
    {
        unsigned u0[16], u1[16];
        float ss0 = 0.f, ss1 = 0.f;
#pragma unroll
        for (int i = 0; i < 16; i++) {
            const float a = ScT[(lane + 32 * i) * 17 + rw];
            const float b = ScT[(lane + 32 * i) * 17 + rw + 1];
            u0[i] = __float_as_uint(a); ss0 += a;
            u1[i] = __float_as_uint(b); ss1 += b;
        }
        // lockstep binary searches (REDUXes back-to-back hide latency)
        unsigned lo0 = 0u, hi0 = 0x7F800000u, lo1 = 0u, hi1 = 0x7F800000u;
#pragma unroll 1
        for (int it = 0; it < 31; it++) {
            const unsigned mid0 = lo0 + ((hi0 - lo0 + 1u) >> 1);
            const unsigned mid1 = lo1 + ((hi1 - lo1 + 1u) >> 1);
            int c0 = 0, c1 = 0;
#pragma unroll
            for (int i = 0; i < 16; i++) {
                c0 += (u0[i] >= mid0);
                c1 += (u1[i] >= mid1);
            }
            c0 = __reduce_add_sync(0xffffffffu, c0);
            c1 = __reduce_add_sync(0xffffffffu, c1);
            if (lo0 < hi0) { if (c0 >= KTOP) lo0 = mid0; else hi0 = mid0 - 1u; }
            if (lo1 < hi1) { if (c1 >= KTOP) lo1 = mid1; else hi1 = mid1 - 1u; }
        }
        const unsigned T0 = lo0, T1 = lo1;
        int   cg0 = 0, cg1 = 0;
        float ts0 = 0.f, ts1 = 0.f;
#pragma unroll
        for (int i = 0; i < 16; i++) {
            if (u0[i] > T0) { cg0++; ts0 += __uint_as_float(u0[i]); }
            if (u1[i] > T1) { cg1++; ts1 += __uint_as_float(u1[i]); }
        }
        cg0 = __reduce_add_sync(0xffffffffu, cg0);
        cg1 = __reduce_add_sync(0xffffffffu, cg1);
#pragma unroll
        for (int o = 16; o; o >>= 1) {
            ts0 += __shfl_xor_sync(0xffffffffu, ts0, o);
            ss0 += __shfl_xor_sync(0xffffffffu, ss0, o);
            ts1 += __shfl_xor_sync(0xffffffffu, ts1, o);
            ss1 += __shfl_xor_sync(0xffffffffu, ss1, o);
        }
        ts0 += (float)(KTOP - cg0) * __uint_as_float(T0);
        ts1 += (float)(KTOP - cg1) * __uint_as_float(T1);
        const float inv0 = 1.0f / (ts0 + 1e-8f * (ss0 + 1e-8f));
        const float inv1 = 1.0f / (ts1 + 1e-8f * (ss1 + 1e-8f));

        // compaction, row rw then rw+1 (ballot order deterministic)
        {
            uint32_t* Lr = L + rw * 52;
            int base = 0;
            int brem = KTOP - cg0;
#pragma unroll
            for (int i = 0; i < 16; i++) {
                const bool gt = (u0[i] > T0);
                const bool eq = (u0[i] == T0);
                const unsigned eqm = __ballot_sync(0xffffffffu, eq);
                const bool teq = eq && (__popc(eqm & ltmask) < brem);
                const unsigned selm = __ballot_sync(0xffffffffu, gt || teq);
                if (gt || teq) {
                    const int pos = base + __popc(selm & ltmask);
                    const float w = __uint_as_float(u0[i]) * inv0;
                    Lr[pos] = (__float_as_uint(w) & ~511u) | (unsigned)(lane + 32 * i);
                }
                base += __popc(selm);
                const int nties = __popc(eqm);
                brem -= (nties < brem) ? nties : brem;
            }
        }
        {
            uint32_t* Lr = L + (rw + 1) * 52;
            int base = 0;
            int brem = KTOP - cg1;
#pragma unroll
            for (int i = 0; i < 16; i++) {
                const bool gt = (u1[i] > T1);
                const bool eq = (u1[i] == T1);
                const unsigned eqm = __ballot_sync(0xffffffffu, eq);
                const bool teq = eq && (__popc(eqm & ltmask) < brem);
                const unsigned selm = __ballot_sync(0xffffffffu, gt || teq);
                if (gt || teq) {
                    const int pos = base + __popc(selm & ltmask);
                    const float w = __uint_as_float(u1[i]) * inv1;
                    Lr[pos] = (__float_as_uint(w) & ~511u) | (unsigned)(lane + 32 * i);
                }
                base += __popc(selm);
                const int nties = __popc(eqm);
                brem -= (nties < brem) ? nties : brem;
            }
        }
    }
    __syncwarp();

    // ---- phase 3: fused gather for both rows (6 loads in flight) ----
    {
        const uint32_t* L0 = L + rw * 52;
        const uint32_t* L1 = L0 + 52;
        float2 a0[3] = {{0.f,0.f},{0.f,0.f},{0.f,0.f}};
        float2 a1[3] = {{0.f,0.f},{0.f,0.f},{0.f,0.f}};
#pragma unroll 3
        for (int e = 0; e < KTOP; e++) {
            const uint32_t b0 = L0[e], b1 = L1[e];
            const float w0 = __uint_as_float(b0 & ~511u);
            const float w1 = __uint_as_float(b1 & ~511u);
            const float2 va = *(const float2*)&g_V[(b0 & 511u) * DMODEL + h * DH + (lane << 1)];
            const float2 vb = *(const float2*)&g_V[(b1 & 511u) * DMODEL + h * DH + (lane << 1)];
            float2& x0 = a0[e % 3];
            float2& x1 = a1[e % 3];
            x0.x = fmaf(w0, va.x, x0.x); x0.y = fmaf(w0, va.y, x0.y);
            x1.x = fmaf(w1, vb.x, x1.x); x1.y = fmaf(w1, vb.y, x1.y);
        }
        float2 o0 = {a0[0].x + a0[1].x + a0[2].x, a0[0].y + a0[1].y + a0[2].y};
        float2 o1 = {a1[0].x + a1[1].x + a1[2].x, a1[0].y + a1[1].y + a1[2].y};
        *(float2*)&g_ctx[(row0 + rw) * DMODEL + h * DH + (lane << 1)]     = o0;
        *(float2*)&g_ctx[(row0 + rw + 1) * DMODEL + h * DH + (lane << 1)] = o1;
    }
}

// ---------------------------------------------------------------------------
extern "C" void kernel_launch(void* const* d_in, const int* in_sizes, int n_in,
                              void* d_out, int out_size)
{
    const float* x  = (const float*)d_in[0];
    const float* Wq = (const float*)d_in[1];
    const float* Wk = (const float*)d_in[2];
    const float* Wv = (const float*)d_in[3];
    const float* Wo = (const float*)d_in[4];
    float* out = (float*)d_out;

    cudaFuncSetAttribute(qkv_part, cudaFuncAttributeMaxDynamicSharedMemorySize, GEMM_SMEM_BYTES);
    cudaFuncSetAttribute(out_part, cudaFuncAttributeMaxDynamicSharedMemorySize, MMA_SMEM_BYTES);
    cudaFuncSetAttribute(attn_kernel, cudaFuncAttributeMaxDynamicSharedMemorySize, ATTN_SMEM_BYTES);

    qkv_part<<<dim3(8, 4, 12), 128, GEMM_SMEM_BYTES>>>(x, Wq, Wk, Wv);
    reduce_qkv<<<768, 256>>>();
    attn_kernel<<<dim3(32, 8), 256, ATTN_SMEM_BYTES>>>();
    out_part<<<dim3(8, 4, 8), 256, MMA_SMEM_BYTES>>>(Wo);
    reduce_out<<<256, 256>>>(out);
}